// round 2
// baseline (speedup 1.0000x reference)
#include <cuda_runtime.h>
#include <math.h>

#define T_  512
#define B_  64
#define I_  1024
#define H_  1024
#define NG_ 4096               // 4*H
#define M_  (T_ * B_)          // 32768

// Scratch (allocation-free rule: __device__ globals)
__device__ float g_gx[(size_t)M_ * NG_];   // 512 MB: precomputed x@W_ih^T + biases
__device__ float g_c[B_ * H_];             // cell state across step launches

// ---------------- packed fp32x2 helpers (FFMA2: 2x fp32 FMA rate on sm_103a) ----
static __device__ __forceinline__ void ffma2(unsigned long long& c,
                                             unsigned long long a,
                                             unsigned long long b) {
    asm("fma.rn.f32x2 %0, %1, %2, %0;" : "+l"(c) : "l"(a), "l"(b));
}
static __device__ __forceinline__ void unpack2(unsigned long long v, float& lo, float& hi) {
    asm("mov.b64 {%0, %1}, %2;" : "=f"(lo), "=f"(hi) : "l"(v));
}

// =====================================================================
// Kernel A: Gx[m][n] = sum_k X[m][k] * Wih[n][k] + (bih[n] + bhh[n])
// M=32768, N=4096, K=1024.  Tile 128x128, BK=16, 256 threads.
// Per-thread: 8 rows x 8 cols, accumulators packed as row-pairs (f32x2).
// B-operand stored duplicated in smem -> inner loop is pure LDS + FFMA2.
// =====================================================================
__global__ __launch_bounds__(256)
void gemm_x_kernel(const float* __restrict__ X, const float* __restrict__ W,
                   const float* __restrict__ bih, const float* __restrict__ bhh)
{
    __shared__ __align__(16) float  Xs[16][128];    // [k][m]
    __shared__ __align__(16) float2 Wsd[16][128];   // [k][n], value duplicated

    const int tid = threadIdx.x;
    const int m0 = blockIdx.y * 128;
    const int n0 = blockIdx.x * 128;
    const int tx = tid & 15;       // 16 col-groups
    const int ty = tid >> 4;       // 16 row-groups (8 rows each)

    // loaders: 128 rows x 16 k per tile, each thread 2x float4 along k
    const int lr = tid >> 1;          // 0..127
    const int lk = (tid & 1) * 8;     // 0 or 8

    const float* Xg = X + (size_t)(m0 + lr) * I_ + lk;
    const float* Wg = W + (size_t)(n0 + lr) * I_ + lk;

    float4 xr0 = *(const float4*)(Xg);
    float4 xr1 = *(const float4*)(Xg + 4);
    float4 wr0 = *(const float4*)(Wg);
    float4 wr1 = *(const float4*)(Wg + 4);

    unsigned long long acc[4][8];
    #pragma unroll
    for (int i = 0; i < 4; ++i)
        #pragma unroll
        for (int j = 0; j < 8; ++j) acc[i][j] = 0ull;

    const int NT = I_ / 16;
    for (int kt = 0; kt < NT; ++kt) {
        Xs[lk + 0][lr] = xr0.x; Xs[lk + 1][lr] = xr0.y;
        Xs[lk + 2][lr] = xr0.z; Xs[lk + 3][lr] = xr0.w;
        Xs[lk + 4][lr] = xr1.x; Xs[lk + 5][lr] = xr1.y;
        Xs[lk + 6][lr] = xr1.z; Xs[lk + 7][lr] = xr1.w;
        Wsd[lk + 0][lr] = make_float2(wr0.x, wr0.x);
        Wsd[lk + 1][lr] = make_float2(wr0.y, wr0.y);
        Wsd[lk + 2][lr] = make_float2(wr0.z, wr0.z);
        Wsd[lk + 3][lr] = make_float2(wr0.w, wr0.w);
        Wsd[lk + 4][lr] = make_float2(wr1.x, wr1.x);
        Wsd[lk + 5][lr] = make_float2(wr1.y, wr1.y);
        Wsd[lk + 6][lr] = make_float2(wr1.z, wr1.z);
        Wsd[lk + 7][lr] = make_float2(wr1.w, wr1.w);
        __syncthreads();

        if (kt + 1 < NT) {   // prefetch next tile (overlaps compute)
            const float* xp = Xg + (size_t)(kt + 1) * 16;
            const float* wp = Wg + (size_t)(kt + 1) * 16;
            xr0 = *(const float4*)(xp);
            xr1 = *(const float4*)(xp + 4);
            wr0 = *(const float4*)(wp);
            wr1 = *(const float4*)(wp + 4);
        }

        #pragma unroll
        for (int k = 0; k < 16; ++k) {
            ulonglong2 va0 = *(const ulonglong2*)&Xs[k][ty * 8];
            ulonglong2 va1 = *(const ulonglong2*)&Xs[k][ty * 8 + 4];
            unsigned long long a2[4] = { va0.x, va0.y, va1.x, va1.y };
            unsigned long long bd[8];
            #pragma unroll
            for (int q = 0; q < 4; ++q) {
                ulonglong2 vb = *(const ulonglong2*)&Wsd[k][q * 32 + 2 * tx];
                bd[2 * q]     = vb.x;
                bd[2 * q + 1] = vb.y;
            }
            #pragma unroll
            for (int rp = 0; rp < 4; ++rp)
                #pragma unroll
                for (int c = 0; c < 8; ++c)
                    ffma2(acc[rp][c], a2[rp], bd[c]);
        }
        __syncthreads();
    }

    // epilogue: add bias, store
    #pragma unroll
    for (int c = 0; c < 8; ++c) {
        const int col = n0 + 32 * (c >> 1) + 2 * tx + (c & 1);
        const float bias = bih[col] + bhh[col];
        #pragma unroll
        for (int rp = 0; rp < 4; ++rp) {
            float v0, v1;
            unpack2(acc[rp][c], v0, v1);
            const int row = m0 + ty * 8 + 2 * rp;
            g_gx[(size_t)row * NG_ + col]       = v0 + bias;
            g_gx[(size_t)(row + 1) * NG_ + col] = v1 + bias;
        }
    }
}

// =====================================================================
// One reverse-scan step. 128 blocks x 256 threads.
// Block bid owns hidden units n0 = bid*8 (8 units -> 32 gate columns).
// GEMM: C[64 batch x 32 cols] = h_in[64x1024] @ Whh_slice^T, then the
// LSTM cell pointwise update for its 8 units, writing h into ys[t].
// =====================================================================
__global__ __launch_bounds__(256)
void lstm_step_kernel(int t, const float* __restrict__ Whh,
                      const float* __restrict__ h_in,
                      const float* __restrict__ c0, int first,
                      float* __restrict__ h_out)
{
    __shared__ __align__(16) float  hs[32][64];    // [k][batch]
    __shared__ __align__(16) float2 wsd[32][32];   // [k][col], duplicated

    const int tid = threadIdx.x;
    const int n0 = blockIdx.x * 8;
    const int tcx = tid & 15;     // col pair: cols 2*tcx, 2*tcx+1
    const int tcy = tid >> 4;     // rows 4*tcy .. +3

    // loaders
    const int hb = tid >> 2;            // 0..63 batch row
    const int hk = (tid & 3) * 4;       // k: 0,4,8,12 (+16 second vec)
    const int wc = tid >> 3;            // 0..31 col
    const int wk = (tid & 7) * 4;       // 0..28
    const int wrow = (wc >> 3) * H_ + n0 + (wc & 7);   // gate-group*H + unit

    const float* hg = h_in + hb * H_ + hk;
    const float* wg = Whh + (size_t)wrow * H_ + wk;

    float4 h0r = *(const float4*)(hg);
    float4 h1r = *(const float4*)(hg + 16);
    float4 wr  = *(const float4*)(wg);

    unsigned long long acc00 = 0, acc01 = 0, acc10 = 0, acc11 = 0;

    const int NT = H_ / 32;
    for (int kt = 0; kt < NT; ++kt) {
        hs[hk + 0][hb]  = h0r.x; hs[hk + 1][hb]  = h0r.y;
        hs[hk + 2][hb]  = h0r.z; hs[hk + 3][hb]  = h0r.w;
        hs[hk + 16][hb] = h1r.x; hs[hk + 17][hb] = h1r.y;
        hs[hk + 18][hb] = h1r.z; hs[hk + 19][hb] = h1r.w;
        wsd[wk + 0][wc] = make_float2(wr.x, wr.x);
        wsd[wk + 1][wc] = make_float2(wr.y, wr.y);
        wsd[wk + 2][wc] = make_float2(wr.z, wr.z);
        wsd[wk + 3][wc] = make_float2(wr.w, wr.w);
        __syncthreads();

        if (kt + 1 < NT) {
            const float* hp = hg + (size_t)(kt + 1) * 32;
            h0r = *(const float4*)(hp);
            h1r = *(const float4*)(hp + 16);
            wr  = *(const float4*)(wg + (size_t)(kt + 1) * 32);
        }

        #pragma unroll
        for (int k = 0; k < 32; ++k) {
            ulonglong2 va = *(const ulonglong2*)&hs[k][tcy * 4];   // row pairs
            ulonglong2 vb = *(const ulonglong2*)&wsd[k][2 * tcx];  // 2 dup'd cols
            ffma2(acc00, va.x, vb.x);
            ffma2(acc01, va.x, vb.y);
            ffma2(acc10, va.y, vb.x);
            ffma2(acc11, va.y, vb.y);
        }
        __syncthreads();   // also protects hs before gsm reuse below
    }

    // gates = recurrent GEMM + precomputed Gx ; stage in smem (reuse hs)
    float* gsm = &hs[0][0];                         // 64 x 32
    const float* gx = g_gx + (size_t)t * B_ * NG_;
    {
        unsigned long long accs[2][2] = { { acc00, acc01 }, { acc10, acc11 } };
        #pragma unroll
        for (int rp = 0; rp < 2; ++rp) {
            #pragma unroll
            for (int cc = 0; cc < 2; ++cc) {
                float v0, v1;
                unpack2(accs[rp][cc], v0, v1);
                const int c = 2 * tcx + cc;
                const int r = tcy * 4 + rp * 2;
                const int gc = (c >> 3) * H_ + n0 + (c & 7);
                v0 += gx[(size_t)r * NG_ + gc];
                v1 += gx[(size_t)(r + 1) * NG_ + gc];
                gsm[r * 32 + c]       = v0;
                gsm[(r + 1) * 32 + c] = v1;
            }
        }
    }
    __syncthreads();

    // pointwise LSTM cell: each thread owns 2 (batch, unit) pairs
    #pragma unroll
    for (int e = 0; e < 2; ++e) {
        const int idx = tid * 2 + e;       // 0..511
        const int b = idx >> 3;
        const int j = idx & 7;
        const float gi = gsm[b * 32 + j];
        const float gf = gsm[b * 32 + 8 + j];
        const float gg = gsm[b * 32 + 16 + j];
        const float go = gsm[b * 32 + 24 + j];
        const int off = b * H_ + n0 + j;
        const float cp = first ? c0[off] : g_c[off];
        const float si = 1.f / (1.f + expf(-gi));
        const float sf = 1.f / (1.f + expf(-gf));
        const float so = 1.f / (1.f + expf(-go));
        const float tg = tanhf(gg);
        const float cn = sf * cp + si * tg;
        g_c[off] = cn;
        h_out[off] = so * tanhf(cn);
    }
}

// hT = ys[0] (reverse scan), cT = final cell state
__global__ void finalize_kernel(float* __restrict__ out)
{
    const int i = blockIdx.x * blockDim.x + threadIdx.x;
    if (i < B_ * H_) {
        out[(size_t)T_ * B_ * H_ + i]            = out[i];
        out[(size_t)T_ * B_ * H_ + B_ * H_ + i]  = g_c[i];
    }
}

extern "C" void kernel_launch(void* const* d_in, const int* in_sizes, int n_in,
                              void* d_out, int out_size)
{
    const float* x   = (const float*)d_in[0];
    const float* h0  = (const float*)d_in[1];
    const float* c0  = (const float*)d_in[2];
    const float* Wih = (const float*)d_in[3];
    const float* Whh = (const float*)d_in[4];
    const float* bih = (const float*)d_in[5];
    const float* bhh = (const float*)d_in[6];
    float* out = (float*)d_out;

    dim3 gA(NG_ / 128, M_ / 128);       // 32 x 256 blocks, N fastest (L2 reuse)
    gemm_x_kernel<<<gA, 256>>>(x, Wih, bih, bhh);

    for (int t = T_ - 1; t >= 0; --t) {
        const float* hin = (t == T_ - 1) ? h0 : out + (size_t)(t + 1) * B_ * H_;
        float* hout = out + (size_t)t * B_ * H_;
        lstm_step_kernel<<<128, 256>>>(t, Whh, hin, c0, (t == T_ - 1) ? 1 : 0, hout);
    }

    finalize_kernel<<<(B_ * H_ + 255) / 256, 256>>>(out);
}

// round 3
// speedup vs baseline: 1.1206x; 1.1206x over previous
#include <cuda_runtime.h>
#include <math.h>

#define T_  512
#define B_  64
#define I_  1024
#define H_  1024
#define NG_ 4096               // 4*H
#define M_  (T_ * B_)          // 32768

// Scratch (allocation-free rule: __device__ globals)
__device__ float g_gx[(size_t)M_ * NG_];   // 512 MB: precomputed x@W_ih^T + biases
__device__ float g_c[B_ * H_];             // cell state across step launches

// ---------------- packed fp32x2 helpers (FFMA2: 2x fp32 FMA rate on sm_103a) ----
static __device__ __forceinline__ void ffma2(unsigned long long& c,
                                             unsigned long long a,
                                             unsigned long long b) {
    asm("fma.rn.f32x2 %0, %1, %2, %0;" : "+l"(c) : "l"(a), "l"(b));
}
static __device__ __forceinline__ void unpack2(unsigned long long v, float& lo, float& hi) {
    asm("mov.b64 {%0, %1}, %2;" : "=f"(lo), "=f"(hi) : "l"(v));
}

static __device__ __forceinline__ float sigf(float x) {
    return __fdividef(1.f, 1.f + __expf(-x));
}
static __device__ __forceinline__ float tanhfast(float x) {
    return 2.f * __fdividef(1.f, 1.f + __expf(-2.f * x)) - 1.f;
}

// =====================================================================
// Kernel A: Gx[m][n] = sum_k X[m][k] * Wih[n][k] + (bih[n] + bhh[n])
// M=32768, N=4096, K=1024.  Tile 128x128, BK=16, 256 threads.
// (unchanged from R1 — measured near the FFMA2 issue roofline)
// =====================================================================
__global__ __launch_bounds__(256)
void gemm_x_kernel(const float* __restrict__ X, const float* __restrict__ W,
                   const float* __restrict__ bih, const float* __restrict__ bhh)
{
    __shared__ __align__(16) float  Xs[16][128];    // [k][m]
    __shared__ __align__(16) float2 Wsd[16][128];   // [k][n], value duplicated

    const int tid = threadIdx.x;
    const int m0 = blockIdx.y * 128;
    const int n0 = blockIdx.x * 128;
    const int tx = tid & 15;       // 16 col-groups
    const int ty = tid >> 4;       // 16 row-groups (8 rows each)

    const int lr = tid >> 1;          // 0..127
    const int lk = (tid & 1) * 8;     // 0 or 8

    const float* Xg = X + (size_t)(m0 + lr) * I_ + lk;
    const float* Wg = W + (size_t)(n0 + lr) * I_ + lk;

    float4 xr0 = *(const float4*)(Xg);
    float4 xr1 = *(const float4*)(Xg + 4);
    float4 wr0 = *(const float4*)(Wg);
    float4 wr1 = *(const float4*)(Wg + 4);

    unsigned long long acc[4][8];
    #pragma unroll
    for (int i = 0; i < 4; ++i)
        #pragma unroll
        for (int j = 0; j < 8; ++j) acc[i][j] = 0ull;

    const int NT = I_ / 16;
    for (int kt = 0; kt < NT; ++kt) {
        Xs[lk + 0][lr] = xr0.x; Xs[lk + 1][lr] = xr0.y;
        Xs[lk + 2][lr] = xr0.z; Xs[lk + 3][lr] = xr0.w;
        Xs[lk + 4][lr] = xr1.x; Xs[lk + 5][lr] = xr1.y;
        Xs[lk + 6][lr] = xr1.z; Xs[lk + 7][lr] = xr1.w;
        Wsd[lk + 0][lr] = make_float2(wr0.x, wr0.x);
        Wsd[lk + 1][lr] = make_float2(wr0.y, wr0.y);
        Wsd[lk + 2][lr] = make_float2(wr0.z, wr0.z);
        Wsd[lk + 3][lr] = make_float2(wr0.w, wr0.w);
        Wsd[lk + 4][lr] = make_float2(wr1.x, wr1.x);
        Wsd[lk + 5][lr] = make_float2(wr1.y, wr1.y);
        Wsd[lk + 6][lr] = make_float2(wr1.z, wr1.z);
        Wsd[lk + 7][lr] = make_float2(wr1.w, wr1.w);
        __syncthreads();

        if (kt + 1 < NT) {
            const float* xp = Xg + (size_t)(kt + 1) * 16;
            const float* wp = Wg + (size_t)(kt + 1) * 16;
            xr0 = *(const float4*)(xp);
            xr1 = *(const float4*)(xp + 4);
            wr0 = *(const float4*)(wp);
            wr1 = *(const float4*)(wp + 4);
        }

        #pragma unroll
        for (int k = 0; k < 16; ++k) {
            ulonglong2 va0 = *(const ulonglong2*)&Xs[k][ty * 8];
            ulonglong2 va1 = *(const ulonglong2*)&Xs[k][ty * 8 + 4];
            unsigned long long a2[4] = { va0.x, va0.y, va1.x, va1.y };
            unsigned long long bd[8];
            #pragma unroll
            for (int q = 0; q < 4; ++q) {
                ulonglong2 vb = *(const ulonglong2*)&Wsd[k][q * 32 + 2 * tx];
                bd[2 * q]     = vb.x;
                bd[2 * q + 1] = vb.y;
            }
            #pragma unroll
            for (int rp = 0; rp < 4; ++rp)
                #pragma unroll
                for (int c = 0; c < 8; ++c)
                    ffma2(acc[rp][c], a2[rp], bd[c]);
        }
        __syncthreads();
    }

    #pragma unroll
    for (int c = 0; c < 8; ++c) {
        const int col = n0 + 32 * (c >> 1) + 2 * tx + (c & 1);
        const float bias = bih[col] + bhh[col];
        #pragma unroll
        for (int rp = 0; rp < 4; ++rp) {
            float v0, v1;
            unpack2(acc[rp][c], v0, v1);
            const int row = m0 + ty * 8 + 2 * rp;
            g_gx[(size_t)row * NG_ + col]       = v0 + bias;
            g_gx[(size_t)(row + 1) * NG_ + col] = v1 + bias;
        }
    }
}

// =====================================================================
// One reverse-scan step. 128 blocks x 512 threads (16 warps = 4/SMSP).
// Block bid owns hidden units n0 = bid*8 (8 units -> 32 gate columns).
// In-block K-split: warps 0-7 reduce k in [0,512), warps 8-15 k in
// [512,1024). Double-buffered smem tiles -> ONE barrier per k-tile.
// Partials combined in smem, then the pointwise LSTM cell (1 elem/thread).
// =====================================================================
__global__ __launch_bounds__(512)
void lstm_step_kernel(int t, const float* __restrict__ Whh,
                      const float* __restrict__ h_in,
                      const float* __restrict__ cinit, int first,
                      float* __restrict__ h_out)
{
    // padded rows: hs row = 68 floats (272B, 16B-aligned strides, conflict-light)
    //              wsd row = 34 float2 (272B)
    __shared__ __align__(16) float  hs[2][2][16][68];   // [half][buf][k][batch]
    __shared__ __align__(16) float2 wsd[2][2][16][34];  // [half][buf][k][col] dup'd

    const int tid  = threadIdx.x;
    const int half = tid >> 8;        // k-split group
    const int ht   = tid & 255;
    const int n0   = blockIdx.x * 8;
    const int kb   = half * 512;

    // compute mapping (within half): 8 outputs = 2 row-pairs x 2 cols
    const int tcx = ht & 15;
    const int tcy = ht >> 4;

    // loaders (within half)
    const int hb = ht >> 2;             // batch row 0..63
    const int hk = (ht & 3) * 4;        // k offset 0,4,8,12
    const int wc = ht >> 3;             // col 0..31
    const int wk = (ht & 7) * 2;        // k offset 0..14
    const int wrow = (wc >> 3) * H_ + n0 + (wc & 7);

    const float* hg = h_in + hb * H_ + kb + hk;
    const float* wg = Whh + (size_t)wrow * H_ + kb + wk;

    float4 h4 = *(const float4*)(hg);
    float2 w2 = *(const float2*)(wg);

    unsigned long long acc00 = 0, acc01 = 0, acc10 = 0, acc11 = 0;

    #pragma unroll 2
    for (int kt = 0; kt < 32; ++kt) {
        const int buf = kt & 1;
        hs[half][buf][hk + 0][hb] = h4.x;
        hs[half][buf][hk + 1][hb] = h4.y;
        hs[half][buf][hk + 2][hb] = h4.z;
        hs[half][buf][hk + 3][hb] = h4.w;
        wsd[half][buf][wk + 0][wc] = make_float2(w2.x, w2.x);
        wsd[half][buf][wk + 1][wc] = make_float2(w2.y, w2.y);
        __syncthreads();   // single barrier per tile (double-buffered)

        if (kt + 1 < 32) {
            h4 = *(const float4*)(hg + (kt + 1) * 16);
            w2 = *(const float2*)(wg + (kt + 1) * 16);
        }

        #pragma unroll
        for (int k = 0; k < 16; ++k) {
            ulonglong2 va = *(const ulonglong2*)&hs[half][buf][k][tcy * 4];
            ulonglong2 vb = *(const ulonglong2*)&wsd[half][buf][k][2 * tcx];
            ffma2(acc00, va.x, vb.x);
            ffma2(acc01, va.x, vb.y);
            ffma2(acc10, va.y, vb.x);
            ffma2(acc11, va.y, vb.y);
        }
    }
    __syncthreads();   // all reads of hs/wsd done before reuse as partial store

    // write partial gate tile [64 x 32] into this half's hs region
    float* gp = &hs[half][0][0][0];
    {
        float v0, v1;
        const int ca = 2 * tcx, cb = 2 * tcx + 1;
        const int r0 = tcy * 4, r1 = tcy * 4 + 2;
        unpack2(acc00, v0, v1); gp[r0 * 32 + ca] = v0; gp[(r0 + 1) * 32 + ca] = v1;
        unpack2(acc01, v0, v1); gp[r0 * 32 + cb] = v0; gp[(r0 + 1) * 32 + cb] = v1;
        unpack2(acc10, v0, v1); gp[r1 * 32 + ca] = v0; gp[(r1 + 1) * 32 + ca] = v1;
        unpack2(acc11, v0, v1); gp[r1 * 32 + cb] = v0; gp[(r1 + 1) * 32 + cb] = v1;
    }
    __syncthreads();

    // pointwise LSTM cell: thread tid owns (batch b, unit j)
    const float* gp0 = &hs[0][0][0][0];
    const float* gp1 = &hs[1][0][0][0];
    const float* gx  = g_gx + (size_t)t * B_ * NG_;
    {
        const int b = tid >> 3;
        const int j = tid & 7;
        const int base = b * 32 + j;
        const size_t gxb = (size_t)b * NG_ + n0 + j;
        const float gi = gp0[base]      + gp1[base]      + gx[gxb];
        const float gf = gp0[base + 8]  + gp1[base + 8]  + gx[gxb + H_];
        const float gg = gp0[base + 16] + gp1[base + 16] + gx[gxb + 2 * H_];
        const float go = gp0[base + 24] + gp1[base + 24] + gx[gxb + 3 * H_];
        const int off = b * H_ + n0 + j;
        const float cp = first ? cinit[off] : g_c[off];
        const float si = sigf(gi);
        const float sf = sigf(gf);
        const float so = sigf(go);
        const float tg = tanhfast(gg);
        const float cn = sf * cp + si * tg;
        g_c[off] = cn;
        h_out[off] = so * tanhfast(cn);
    }
}

// hT = ys[0] (reverse scan), cT = final cell state
__global__ void finalize_kernel(float* __restrict__ out)
{
    const int i = blockIdx.x * blockDim.x + threadIdx.x;
    if (i < B_ * H_) {
        out[(size_t)T_ * B_ * H_ + i]            = out[i];
        out[(size_t)T_ * B_ * H_ + B_ * H_ + i]  = g_c[i];
    }
}

extern "C" void kernel_launch(void* const* d_in, const int* in_sizes, int n_in,
                              void* d_out, int out_size)
{
    const float* x   = (const float*)d_in[0];
    const float* h0  = (const float*)d_in[1];
    const float* c0  = (const float*)d_in[2];
    const float* Wih = (const float*)d_in[3];
    const float* Whh = (const float*)d_in[4];
    const float* bih = (const float*)d_in[5];
    const float* bhh = (const float*)d_in[6];
    float* out = (float*)d_out;

    dim3 gA(NG_ / 128, M_ / 128);       // 32 x 256 blocks
    gemm_x_kernel<<<gA, 256>>>(x, Wih, bih, bhh);

    for (int t = T_ - 1; t >= 0; --t) {
        const float* hin = (t == T_ - 1) ? h0 : out + (size_t)(t + 1) * B_ * H_;
        float* hout = out + (size_t)t * B_ * H_;
        lstm_step_kernel<<<128, 512>>>(t, Whh, hin, c0, (t == T_ - 1) ? 1 : 0, hout);
    }

    finalize_kernel<<<(B_ * H_ + 255) / 256, 256>>>(out);
}

// round 9
// speedup vs baseline: 1.6312x; 1.4557x over previous
#include <cuda_runtime.h>
#include <cuda_bf16.h>
#include <stdint.h>
#include <math.h>

#define T_  512
#define B_  64
#define I_  1024
#define H_  1024
#define NG_ 4096               // 4*H
#define M_  (T_ * B_)          // 32768

// ---------------- scratch (__device__ globals; no allocations allowed) -------
__device__ float g_gx[(size_t)M_ * NG_];          // x@W_ih^T + biases (fp32)
__device__ float g_c[B_ * H_];                    // cell state
__device__ __nv_bfloat16 g_wh_hi[(size_t)NG_ * H_];   // Whh bf16 hi
__device__ __nv_bfloat16 g_wh_lo[(size_t)NG_ * H_];   // Whh bf16 lo
__device__ __nv_bfloat16 g_hh[2][B_ * H_];        // h bf16 hi (ping-pong)
__device__ __nv_bfloat16 g_hl[2][B_ * H_];        // h bf16 lo (ping-pong)

// ---------------- fp32x2 helpers (gemm_x) ------------------------------------
static __device__ __forceinline__ void ffma2(unsigned long long& c,
                                             unsigned long long a,
                                             unsigned long long b) {
    asm("fma.rn.f32x2 %0, %1, %2, %0;" : "+l"(c) : "l"(a), "l"(b));
}
static __device__ __forceinline__ void unpack2(unsigned long long v, float& lo, float& hi) {
    asm("mov.b64 {%0, %1}, %2;" : "=f"(lo), "=f"(hi) : "l"(v));
}
static __device__ __forceinline__ float sigf(float x) {
    return __fdividef(1.f, 1.f + __expf(-x));
}
static __device__ __forceinline__ float tanhfast(float x) {
    return 2.f * __fdividef(1.f, 1.f + __expf(-2.f * x)) - 1.f;
}
static __device__ __forceinline__ uint32_t smem_u32(const void* p) {
    uint32_t a;
    asm("{ .reg .u64 t; cvta.to.shared.u64 t, %1; cvt.u32.u64 %0, t; }" : "=r"(a) : "l"(p));
    return a;
}

// ---------------- portable tensor-core primitives (sm_80 PTX) ----------------
#define LDSM4(r, addr) \
    asm volatile("ldmatrix.sync.aligned.m8n8.x4.shared.b16 {%0,%1,%2,%3}, [%4];" \
        : "=r"((r)[0]), "=r"((r)[1]), "=r"((r)[2]), "=r"((r)[3]) : "r"(addr))

#define MMA16816(d, a, b0r, b1r) \
    asm volatile("mma.sync.aligned.m16n8k16.row.col.f32.bf16.bf16.f32 " \
        "{%0,%1,%2,%3}, {%4,%5,%6,%7}, {%8,%9}, {%0,%1,%2,%3};" \
        : "+f"((d)[0]), "+f"((d)[1]), "+f"((d)[2]), "+f"((d)[3]) \
        : "r"((a)[0]), "r"((a)[1]), "r"((a)[2]), "r"((a)[3]), "r"(b0r), "r"(b1r))

// =====================================================================
// Kernel A: Gx = X @ W_ih^T + (bih+bhh)   (FFMA2, unchanged)
// =====================================================================
__global__ __launch_bounds__(256)
void gemm_x_kernel(const float* __restrict__ X, const float* __restrict__ W,
                   const float* __restrict__ bih, const float* __restrict__ bhh)
{
    __shared__ __align__(16) float  Xs[16][128];
    __shared__ __align__(16) float2 Wsd[16][128];

    const int tid = threadIdx.x;
    const int m0 = blockIdx.y * 128;
    const int n0 = blockIdx.x * 128;
    const int tx = tid & 15;
    const int ty = tid >> 4;
    const int lr = tid >> 1;
    const int lk = (tid & 1) * 8;

    const float* Xg = X + (size_t)(m0 + lr) * I_ + lk;
    const float* Wg = W + (size_t)(n0 + lr) * I_ + lk;

    float4 xr0 = *(const float4*)(Xg);
    float4 xr1 = *(const float4*)(Xg + 4);
    float4 wr0 = *(const float4*)(Wg);
    float4 wr1 = *(const float4*)(Wg + 4);

    unsigned long long acc[4][8];
    #pragma unroll
    for (int i = 0; i < 4; ++i)
        #pragma unroll
        for (int j = 0; j < 8; ++j) acc[i][j] = 0ull;

    const int NT = I_ / 16;
    for (int kt = 0; kt < NT; ++kt) {
        Xs[lk + 0][lr] = xr0.x; Xs[lk + 1][lr] = xr0.y;
        Xs[lk + 2][lr] = xr0.z; Xs[lk + 3][lr] = xr0.w;
        Xs[lk + 4][lr] = xr1.x; Xs[lk + 5][lr] = xr1.y;
        Xs[lk + 6][lr] = xr1.z; Xs[lk + 7][lr] = xr1.w;
        Wsd[lk + 0][lr] = make_float2(wr0.x, wr0.x);
        Wsd[lk + 1][lr] = make_float2(wr0.y, wr0.y);
        Wsd[lk + 2][lr] = make_float2(wr0.z, wr0.z);
        Wsd[lk + 3][lr] = make_float2(wr0.w, wr0.w);
        Wsd[lk + 4][lr] = make_float2(wr1.x, wr1.x);
        Wsd[lk + 5][lr] = make_float2(wr1.y, wr1.y);
        Wsd[lk + 6][lr] = make_float2(wr1.z, wr1.z);
        Wsd[lk + 7][lr] = make_float2(wr1.w, wr1.w);
        __syncthreads();

        if (kt + 1 < NT) {
            const float* xp = Xg + (size_t)(kt + 1) * 16;
            const float* wp = Wg + (size_t)(kt + 1) * 16;
            xr0 = *(const float4*)(xp);
            xr1 = *(const float4*)(xp + 4);
            wr0 = *(const float4*)(wp);
            wr1 = *(const float4*)(wp + 4);
        }

        #pragma unroll
        for (int k = 0; k < 16; ++k) {
            ulonglong2 va0 = *(const ulonglong2*)&Xs[k][ty * 8];
            ulonglong2 va1 = *(const ulonglong2*)&Xs[k][ty * 8 + 4];
            unsigned long long a2[4] = { va0.x, va0.y, va1.x, va1.y };
            unsigned long long bd[8];
            #pragma unroll
            for (int q = 0; q < 4; ++q) {
                ulonglong2 vb = *(const ulonglong2*)&Wsd[k][q * 32 + 2 * tx];
                bd[2 * q]     = vb.x;
                bd[2 * q + 1] = vb.y;
            }
            #pragma unroll
            for (int rp = 0; rp < 4; ++rp)
                #pragma unroll
                for (int c = 0; c < 8; ++c)
                    ffma2(acc[rp][c], a2[rp], bd[c]);
        }
        __syncthreads();
    }

    #pragma unroll
    for (int c = 0; c < 8; ++c) {
        const int col = n0 + 32 * (c >> 1) + 2 * tx + (c & 1);
        const float bias = bih[col] + bhh[col];
        #pragma unroll
        for (int rp = 0; rp < 4; ++rp) {
            float v0, v1;
            unpack2(acc[rp][c], v0, v1);
            const int row = m0 + ty * 8 + 2 * rp;
            g_gx[(size_t)row * NG_ + col]       = v0 + bias;
            g_gx[(size_t)(row + 1) * NG_ + col] = v1 + bias;
        }
    }
}

// ---------------- bf16 hi/lo split kernels -----------------------------------
__global__ void split_whh_kernel(const float* __restrict__ W)
{
    const size_t i = (size_t)blockIdx.x * 1024 + threadIdx.x;   // 4096 x 1024
    const float w = W[i];
    const __nv_bfloat16 hi = __float2bfloat16(w);
    g_wh_hi[i] = hi;
    g_wh_lo[i] = __float2bfloat16(w - __bfloat162float(hi));
}
__global__ void split_h0_kernel(const float* __restrict__ h0)
{
    const int i = blockIdx.x * 1024 + threadIdx.x;              // 64 x 1024
    const float v = h0[i];
    const __nv_bfloat16 hi = __float2bfloat16(v);
    g_hh[0][i] = hi;
    g_hl[0][i] = __float2bfloat16(v - __bfloat162float(hi));
}

// =====================================================================
// mma.sync recurrent step. 128 blocks x 256 threads (8 warps).
// Block owns 8 hidden units -> 32 gate cols (col j = gate*8 + unit).
// C[64 x 32] = h[64x1024] @ WhhSlice^T via bf16 hi/lo, 3 MMA terms.
// Warp w: m-tile (w&3)*16, n-half (w>>2)*16 (2 mma n-tiles).
// K in 16 chunks of 64, single-buffer smem + register prefetch.
// =====================================================================
__global__ __launch_bounds__(256)
void lstm_step_mma(int t, const float* __restrict__ cinit, int first,
                   float* __restrict__ h_out)
{
    __shared__ __align__(16) __nv_bfloat16 sAh[64][72];   // 144B rows: LDSM conflict-free
    __shared__ __align__(16) __nv_bfloat16 sAl[64][72];
    __shared__ __align__(16) __nv_bfloat16 sBh[32][72];
    __shared__ __align__(16) __nv_bfloat16 sBl[32][72];
    __shared__ __align__(16) float sC[64][33];

    const int tid  = threadIdx.x;
    const int warp = tid >> 5;
    const int lane = tid & 31;
    const int n0   = blockIdx.x * 8;
    const int inb  = (t + 1) & 1;
    const int outb = t & 1;

    // ---- loader mapping ----
    const int ar = tid >> 2;            // A row (batch) 0..63
    const int av = tid & 3;             // 2 x 16B segments: av, av+4
    const int br = tid >> 3;            // B row (gate col) 0..31
    const int bv = tid & 7;             // 1 x 16B segment
    const int wrow = (br >> 3) * H_ + n0 + (br & 7);

    const __nv_bfloat16* Ah = g_hh[inb] + ar * H_;
    const __nv_bfloat16* Al = g_hl[inb] + ar * H_;
    const __nv_bfloat16* Bh = g_wh_hi + (size_t)wrow * H_;
    const __nv_bfloat16* Bl = g_wh_lo + (size_t)wrow * H_;

    // ---- ldmatrix per-thread addresses ----
    const int wm = (warp & 3) * 16;
    const int wn = (warp >> 2) * 16;
    const uint32_t aoff = (lane >> 4) * 8;                  // k-half within 16
    const uint32_t a_h_addr = smem_u32(&sAh[wm + (lane & 15)][aoff]);
    const uint32_t a_l_addr = smem_u32(&sAl[wm + (lane & 15)][aoff]);
    const int brow = wn + ((lane >> 3) & 1) * 8 + (lane & 7);
    const uint32_t boff = (lane >> 4) * 8;
    const uint32_t b_h_addr = smem_u32(&sBh[brow][boff]);
    const uint32_t b_l_addr = smem_u32(&sBl[brow][boff]);

    float acc0[4] = {0.f, 0.f, 0.f, 0.f};
    float acc1[4] = {0.f, 0.f, 0.f, 0.f};

    // prefetch chunk 0
    uint4 pa0 = *(const uint4*)(Ah + av * 8);
    uint4 pa1 = *(const uint4*)(Ah + av * 8 + 32);
    uint4 pa2 = *(const uint4*)(Al + av * 8);
    uint4 pa3 = *(const uint4*)(Al + av * 8 + 32);
    uint4 pb0 = *(const uint4*)(Bh + bv * 8);
    uint4 pb1 = *(const uint4*)(Bl + bv * 8);

    for (int c = 0; c < 16; ++c) {
        *(uint4*)&sAh[ar][av * 8]      = pa0;
        *(uint4*)&sAh[ar][av * 8 + 32] = pa1;
        *(uint4*)&sAl[ar][av * 8]      = pa2;
        *(uint4*)&sAl[ar][av * 8 + 32] = pa3;
        *(uint4*)&sBh[br][bv * 8]      = pb0;
        *(uint4*)&sBl[br][bv * 8]      = pb1;
        __syncthreads();

        if (c + 1 < 16) {
            const int ko = (c + 1) * 64;
            pa0 = *(const uint4*)(Ah + ko + av * 8);
            pa1 = *(const uint4*)(Ah + ko + av * 8 + 32);
            pa2 = *(const uint4*)(Al + ko + av * 8);
            pa3 = *(const uint4*)(Al + ko + av * 8 + 32);
            pb0 = *(const uint4*)(Bh + ko + bv * 8);
            pb1 = *(const uint4*)(Bl + ko + bv * 8);
        }

        #pragma unroll
        for (int ks = 0; ks < 4; ++ks) {
            uint32_t ah[4], al[4], bh[4], bl[4];
            LDSM4(ah, a_h_addr + ks * 32);
            LDSM4(al, a_l_addr + ks * 32);
            LDSM4(bh, b_h_addr + ks * 32);
            LDSM4(bl, b_l_addr + ks * 32);
            MMA16816(acc0, ah, bh[0], bh[2]);
            MMA16816(acc1, ah, bh[1], bh[3]);
            MMA16816(acc0, ah, bl[0], bl[2]);
            MMA16816(acc1, ah, bl[1], bl[3]);
            MMA16816(acc0, al, bh[0], bh[2]);
            MMA16816(acc1, al, bh[1], bh[3]);
        }
        __syncthreads();
    }

    // ---- stage C tile in smem ----
    {
        const int r0 = wm + (lane >> 2);
        const int cc = wn + 2 * (lane & 3);
        sC[r0][cc]          = acc0[0];
        sC[r0][cc + 1]      = acc0[1];
        sC[r0 + 8][cc]      = acc0[2];
        sC[r0 + 8][cc + 1]  = acc0[3];
        sC[r0][cc + 8]      = acc1[0];
        sC[r0][cc + 9]      = acc1[1];
        sC[r0 + 8][cc + 8]  = acc1[2];
        sC[r0 + 8][cc + 9]  = acc1[3];
    }
    __syncthreads();

    // ---- pointwise LSTM cell: thread handles 2 (batch, unit) elems ----
    const float* gx = g_gx + (size_t)t * B_ * NG_;
    #pragma unroll
    for (int e = 0; e < 2; ++e) {
        const int idx = tid * 2 + e;       // 0..511
        const int b = idx >> 3;
        const int j = idx & 7;
        const size_t gxb = (size_t)b * NG_ + n0 + j;
        const float gi = sC[b][j]      + gx[gxb];
        const float gf = sC[b][8 + j]  + gx[gxb + H_];
        const float gg = sC[b][16 + j] + gx[gxb + 2 * H_];
        const float go = sC[b][24 + j] + gx[gxb + 3 * H_];
        const int off = b * H_ + n0 + j;
        const float cp = first ? cinit[off] : g_c[off];
        const float si = sigf(gi);
        const float sf = sigf(gf);
        const float tg = tanhfast(gg);
        const float so = sigf(go);
        const float cn = sf * cp + si * tg;
        g_c[off] = cn;
        const float hv = so * tanhfast(cn);
        h_out[off] = hv;
        const __nv_bfloat16 hhi = __float2bfloat16(hv);
        g_hh[outb][off] = hhi;
        g_hl[outb][off] = __float2bfloat16(hv - __bfloat162float(hhi));
    }
}

// hT = ys[0] (reverse scan), cT = final cell state
__global__ void finalize_kernel(float* __restrict__ out)
{
    const int i = blockIdx.x * blockDim.x + threadIdx.x;
    if (i < B_ * H_) {
        out[(size_t)T_ * B_ * H_ + i]            = out[i];
        out[(size_t)T_ * B_ * H_ + B_ * H_ + i]  = g_c[i];
    }
}

extern "C" void kernel_launch(void* const* d_in, const int* in_sizes, int n_in,
                              void* d_out, int out_size)
{
    const float* x   = (const float*)d_in[0];
    const float* h0  = (const float*)d_in[1];
    const float* c0  = (const float*)d_in[2];
    const float* Wih = (const float*)d_in[3];
    const float* Whh = (const float*)d_in[4];
    const float* bih = (const float*)d_in[5];
    const float* bhh = (const float*)d_in[6];
    float* out = (float*)d_out;

    split_whh_kernel<<<4096, 1024>>>(Whh);
    split_h0_kernel<<<64, 1024>>>(h0);

    dim3 gA(NG_ / 128, M_ / 128);
    gemm_x_kernel<<<gA, 256>>>(x, Wih, bih, bhh);

    for (int t = T_ - 1; t >= 0; --t) {
        float* hout = out + (size_t)t * B_ * H_;
        lstm_step_mma<<<128, 256>>>(t, c0, (t == T_ - 1) ? 1 : 0, hout);
    }

    finalize_kernel<<<(B_ * H_ + 255) / 256, 256>>>(out);
}

// round 14
// speedup vs baseline: 2.0762x; 1.2728x over previous
#include <cuda_runtime.h>
#include <cuda_bf16.h>
#include <stdint.h>
#include <math.h>

#define T_  512
#define B_  64
#define I_  1024
#define H_  1024
#define NG_ 4096               // 4*H
#define M_  (T_ * B_)          // 32768
#define NBLK 128

// ---------------- scratch (__device__ globals; no allocations allowed) -------
__device__ float g_gx[(size_t)M_ * NG_];          // x@W_ih^T + biases (fp32)
__device__ __nv_bfloat16 g_wh_hi[(size_t)NG_ * H_];   // Whh bf16 hi
__device__ __nv_bfloat16 g_wh_lo[(size_t)NG_ * H_];   // Whh bf16 lo
__device__ __nv_bfloat16 g_hh[2][B_ * H_];        // h bf16 hi (ping-pong)
__device__ __nv_bfloat16 g_hl[2][B_ * H_];        // h bf16 lo (ping-pong)
__device__ unsigned g_bar_count;                  // grid barrier state
__device__ volatile unsigned g_bar_gen;

// ---------------- helpers ----------------------------------------------------
static __device__ __forceinline__ void ffma2(unsigned long long& c,
                                             unsigned long long a,
                                             unsigned long long b) {
    asm("fma.rn.f32x2 %0, %1, %2, %0;" : "+l"(c) : "l"(a), "l"(b));
}
static __device__ __forceinline__ void unpack2(unsigned long long v, float& lo, float& hi) {
    asm("mov.b64 {%0, %1}, %2;" : "=f"(lo), "=f"(hi) : "l"(v));
}
static __device__ __forceinline__ float sigf(float x) {
    return __fdividef(1.f, 1.f + __expf(-x));
}
static __device__ __forceinline__ float tanhfast(float x) {
    return 2.f * __fdividef(1.f, 1.f + __expf(-2.f * x)) - 1.f;
}
static __device__ __forceinline__ uint32_t smem_u32(const void* p) {
    uint32_t a;
    asm("{ .reg .u64 t; cvta.to.shared.u64 t, %1; cvt.u32.u64 %0, t; }" : "=r"(a) : "l"(p));
    return a;
}

// ---------------- portable tensor-core + cp.async (sm_80 PTX) ----------------
#define LDSM4(r, addr) \
    asm volatile("ldmatrix.sync.aligned.m8n8.x4.shared.b16 {%0,%1,%2,%3}, [%4];" \
        : "=r"((r)[0]), "=r"((r)[1]), "=r"((r)[2]), "=r"((r)[3]) : "r"(addr))

#define MMA16816(d, a, b0r, b1r) \
    asm volatile("mma.sync.aligned.m16n8k16.row.col.f32.bf16.bf16.f32 " \
        "{%0,%1,%2,%3}, {%4,%5,%6,%7}, {%8,%9}, {%0,%1,%2,%3};" \
        : "+f"((d)[0]), "+f"((d)[1]), "+f"((d)[2]), "+f"((d)[3]) \
        : "r"((a)[0]), "r"((a)[1]), "r"((a)[2]), "r"((a)[3]), "r"(b0r), "r"(b1r))

#define CPA16(dst, src) \
    asm volatile("cp.async.cg.shared.global [%0], [%1], 16;" :: "r"(dst), "l"(src))
#define CPA_COMMIT() asm volatile("cp.async.commit_group;" ::: "memory")
#define CPA_WAIT(n)  asm volatile("cp.async.wait_group %0;" :: "n"(n) : "memory")

// =====================================================================
// Kernel A: Gx = X @ W_ih^T + (bih+bhh)   (FFMA2, unchanged)
// =====================================================================
__global__ __launch_bounds__(256)
void gemm_x_kernel(const float* __restrict__ X, const float* __restrict__ W,
                   const float* __restrict__ bih, const float* __restrict__ bhh)
{
    __shared__ __align__(16) float  Xs[16][128];
    __shared__ __align__(16) float2 Wsd[16][128];

    const int tid = threadIdx.x;
    const int m0 = blockIdx.y * 128;
    const int n0 = blockIdx.x * 128;
    const int tx = tid & 15;
    const int ty = tid >> 4;
    const int lr = tid >> 1;
    const int lk = (tid & 1) * 8;

    const float* Xg = X + (size_t)(m0 + lr) * I_ + lk;
    const float* Wg = W + (size_t)(n0 + lr) * I_ + lk;

    float4 xr0 = *(const float4*)(Xg);
    float4 xr1 = *(const float4*)(Xg + 4);
    float4 wr0 = *(const float4*)(Wg);
    float4 wr1 = *(const float4*)(Wg + 4);

    unsigned long long acc[4][8];
    #pragma unroll
    for (int i = 0; i < 4; ++i)
        #pragma unroll
        for (int j = 0; j < 8; ++j) acc[i][j] = 0ull;

    const int NT = I_ / 16;
    for (int kt = 0; kt < NT; ++kt) {
        Xs[lk + 0][lr] = xr0.x; Xs[lk + 1][lr] = xr0.y;
        Xs[lk + 2][lr] = xr0.z; Xs[lk + 3][lr] = xr0.w;
        Xs[lk + 4][lr] = xr1.x; Xs[lk + 5][lr] = xr1.y;
        Xs[lk + 6][lr] = xr1.z; Xs[lk + 7][lr] = xr1.w;
        Wsd[lk + 0][lr] = make_float2(wr0.x, wr0.x);
        Wsd[lk + 1][lr] = make_float2(wr0.y, wr0.y);
        Wsd[lk + 2][lr] = make_float2(wr0.z, wr0.z);
        Wsd[lk + 3][lr] = make_float2(wr0.w, wr0.w);
        Wsd[lk + 4][lr] = make_float2(wr1.x, wr1.x);
        Wsd[lk + 5][lr] = make_float2(wr1.y, wr1.y);
        Wsd[lk + 6][lr] = make_float2(wr1.z, wr1.z);
        Wsd[lk + 7][lr] = make_float2(wr1.w, wr1.w);
        __syncthreads();

        if (kt + 1 < NT) {
            const float* xp = Xg + (size_t)(kt + 1) * 16;
            const float* wp = Wg + (size_t)(kt + 1) * 16;
            xr0 = *(const float4*)(xp);
            xr1 = *(const float4*)(xp + 4);
            wr0 = *(const float4*)(wp);
            wr1 = *(const float4*)(wp + 4);
        }

        #pragma unroll
        for (int k = 0; k < 16; ++k) {
            ulonglong2 va0 = *(const ulonglong2*)&Xs[k][ty * 8];
            ulonglong2 va1 = *(const ulonglong2*)&Xs[k][ty * 8 + 4];
            unsigned long long a2[4] = { va0.x, va0.y, va1.x, va1.y };
            unsigned long long bd[8];
            #pragma unroll
            for (int q = 0; q < 4; ++q) {
                ulonglong2 vb = *(const ulonglong2*)&Wsd[k][q * 32 + 2 * tx];
                bd[2 * q]     = vb.x;
                bd[2 * q + 1] = vb.y;
            }
            #pragma unroll
            for (int rp = 0; rp < 4; ++rp)
                #pragma unroll
                for (int c = 0; c < 8; ++c)
                    ffma2(acc[rp][c], a2[rp], bd[c]);
        }
        __syncthreads();
    }

    #pragma unroll
    for (int c = 0; c < 8; ++c) {
        const int col = n0 + 32 * (c >> 1) + 2 * tx + (c & 1);
        const float bias = bih[col] + bhh[col];
        #pragma unroll
        for (int rp = 0; rp < 4; ++rp) {
            float v0, v1;
            unpack2(acc[rp][c], v0, v1);
            const int row = m0 + ty * 8 + 2 * rp;
            g_gx[(size_t)row * NG_ + col]       = v0 + bias;
            g_gx[(size_t)(row + 1) * NG_ + col] = v1 + bias;
        }
    }
}

// ---------------- bf16 hi/lo split kernels -----------------------------------
__global__ void split_whh_kernel(const float* __restrict__ W)
{
    const size_t i = (size_t)blockIdx.x * 1024 + threadIdx.x;   // 4096 x 1024
    const float w = W[i];
    const __nv_bfloat16 hi = __float2bfloat16(w);
    g_wh_hi[i] = hi;
    g_wh_lo[i] = __float2bfloat16(w - __bfloat162float(hi));
}
__global__ void split_h0_kernel(const float* __restrict__ h0)
{
    const int i = blockIdx.x * 1024 + threadIdx.x;              // 64 x 1024
    const float v = h0[i];
    const __nv_bfloat16 hi = __float2bfloat16(v);
    g_hh[0][i] = hi;
    g_hl[0][i] = __float2bfloat16(v - __bfloat162float(hi));
}

// =====================================================================
// Persistent reverse-scan kernel. 128 blocks x 256 threads, 1 block/SM.
// Whh hi/lo slice (32 gate cols x 1024) resident in smem for all steps.
// Per step: h(hi/lo) streamed via 4-stage cp.async; bf16 hi/lo 3-term
// mma; cell state in registers; global spin barrier between steps.
// =====================================================================
#define OFF_BH 0
#define OFF_BL 66048
#define OFF_A  132096          // 4 stages x 18432 (hi 9216 + lo 9216)
#define OFF_C  205824          // 64 x 33 floats
#define SMEM_TOT 214272
#define BROW_STRIDE 2064       // 1024 bf16 + 8 pad (conflict-free ldmatrix)
#define AROW_STRIDE 144        // 64 bf16 + 8 pad
#define STAGE_BYTES 18432

static __device__ __forceinline__ void grid_barrier()
{
    __threadfence();
    __syncthreads();
    if (threadIdx.x == 0) {
        const unsigned seen = g_bar_gen;
        if (atomicAdd(&g_bar_count, 1) == NBLK - 1) {
            atomicExch(&g_bar_count, 0);
            __threadfence();
            g_bar_gen = seen + 1;
        } else {
            while (g_bar_gen == seen) { }
            __threadfence();
        }
    }
    __syncthreads();
}

__global__ __launch_bounds__(256)
void lstm_persist(const float* __restrict__ cinit, float* __restrict__ out)
{
    extern __shared__ __align__(1024) char sm[];
    const uint32_t smb = smem_u32(sm);
    const int tid  = threadIdx.x;
    const int warp = tid >> 5;
    const int lane = tid & 31;
    const int n0   = blockIdx.x * 8;

    // ---- load resident Whh slice (hi/lo) ----
    for (int i = tid; i < 4096; i += 256) {     // 32 rows x 128 segs of 16B
        const int r = i >> 7, s = i & 127;
        const size_t grow = (size_t)((r >> 3) * H_ + n0 + (r & 7)) * H_;
        *(uint4*)(sm + OFF_BH + r * BROW_STRIDE + s * 16) =
            *(const uint4*)(g_wh_hi + grow + s * 8);
        *(uint4*)(sm + OFF_BL + r * BROW_STRIDE + s * 16) =
            *(const uint4*)(g_wh_lo + grow + s * 8);
    }

    // ---- per-thread constants ----
    const int wm = (warp & 3) * 16;
    const int wn = (warp >> 2) * 16;
    const int brow = wn + ((lane >> 3) & 1) * 8 + (lane & 7);
    const uint32_t bBaseH = smb + OFF_BH + brow * BROW_STRIDE + (lane >> 4) * 16;
    const uint32_t bBaseL = smb + OFF_BL + brow * BROW_STRIDE + (lane >> 4) * 16;
    const uint32_t aFrag  = (wm + (lane & 15)) * AROW_STRIDE + (lane >> 4) * 16;

    const int arow = tid >> 2;              // A loader: batch row 0..63
    const int segB = (tid & 3) * 16;        // byte offset of 16B seg
    const int segE = (tid & 3) * 8;         // elem offset

    // epilogue ownership (static across steps): 2 (batch,unit) elems / thread
    const int b0 = (tid * 2) >> 3,     j0 = (tid * 2) & 7;
    const int b1 = (tid * 2 + 1) >> 3, j1 = (tid * 2 + 1) & 7;
    const int off0 = b0 * H_ + n0 + j0;
    const int off1 = b1 * H_ + n0 + j1;
    float creg0 = cinit[off0];
    float creg1 = cinit[off1];

    float* sC = (float*)(sm + OFF_C);
    __syncthreads();

    for (int t = T_ - 1; t >= 0; --t) {
        const int inb = (t + 1) & 1, outb = t & 1;
        const __nv_bfloat16* Ah = g_hh[inb] + (size_t)arow * H_ + segE;
        const __nv_bfloat16* Al = g_hl[inb] + (size_t)arow * H_ + segE;
        const uint32_t aDst = smb + OFF_A + arow * AROW_STRIDE + segB;

        // prologue: chunks 0..2 into stages 0..2
        #pragma unroll
        for (int s = 0; s < 3; ++s) {
            const uint32_t d = aDst + s * STAGE_BYTES;
            CPA16(d,            Ah + s * 64);
            CPA16(d + 64,       Ah + s * 64 + 32);
            CPA16(d + 9216,     Al + s * 64);
            CPA16(d + 9216 + 64, Al + s * 64 + 32);
            CPA_COMMIT();
        }

        float acc0[4] = {0.f, 0.f, 0.f, 0.f};
        float acc1[4] = {0.f, 0.f, 0.f, 0.f};

        for (int c = 0; c < 16; ++c) {
            if (c < 14)       CPA_WAIT(2);
            else if (c == 14) CPA_WAIT(1);
            else              CPA_WAIT(0);
            __syncthreads();
            if (c + 3 < 16) {
                const int cc = c + 3;
                const uint32_t d = aDst + (cc & 3) * STAGE_BYTES;
                CPA16(d,            Ah + cc * 64);
                CPA16(d + 64,       Ah + cc * 64 + 32);
                CPA16(d + 9216,     Al + cc * 64);
                CPA16(d + 9216 + 64, Al + cc * 64 + 32);
                CPA_COMMIT();
            }
            const uint32_t aH = smb + OFF_A + (c & 3) * STAGE_BYTES + aFrag;
            const uint32_t aL = aH + 9216;
            const uint32_t bH = bBaseH + c * 128;
            const uint32_t bL = bBaseL + c * 128;
            #pragma unroll
            for (int ks = 0; ks < 4; ++ks) {
                uint32_t ah[4], al[4], bh[4], bl[4];
                LDSM4(ah, aH + ks * 32);
                LDSM4(al, aL + ks * 32);
                LDSM4(bh, bH + ks * 32);
                LDSM4(bl, bL + ks * 32);
                MMA16816(acc0, ah, bh[0], bh[2]);
                MMA16816(acc1, ah, bh[1], bh[3]);
                MMA16816(acc0, ah, bl[0], bl[2]);
                MMA16816(acc1, ah, bl[1], bl[3]);
                MMA16816(acc0, al, bh[0], bh[2]);
                MMA16816(acc1, al, bh[1], bh[3]);
            }
        }

        // ---- stage C tile ----
        {
            const int r0 = wm + (lane >> 2);
            const int cc = wn + 2 * (lane & 3);
            sC[r0 * 33 + cc]           = acc0[0];
            sC[r0 * 33 + cc + 1]       = acc0[1];
            sC[(r0 + 8) * 33 + cc]     = acc0[2];
            sC[(r0 + 8) * 33 + cc + 1] = acc0[3];
            sC[r0 * 33 + cc + 8]       = acc1[0];
            sC[r0 * 33 + cc + 9]       = acc1[1];
            sC[(r0 + 8) * 33 + cc + 8] = acc1[2];
            sC[(r0 + 8) * 33 + cc + 9] = acc1[3];
        }
        __syncthreads();

        // ---- cell update (2 elems/thread, c-state in registers) ----
        const float* gx = g_gx + (size_t)t * B_ * NG_;
        float* h_out = out + (size_t)t * B_ * H_;
        #pragma unroll
        for (int e = 0; e < 2; ++e) {
            const int b = e ? b1 : b0;
            const int j = e ? j1 : j0;
            const int off = e ? off1 : off0;
            const size_t gxb = (size_t)b * NG_ + n0 + j;
            const float gi = sC[b * 33 + j]      + gx[gxb];
            const float gf = sC[b * 33 + 8 + j]  + gx[gxb + H_];
            const float gg = sC[b * 33 + 16 + j] + gx[gxb + 2 * H_];
            const float go = sC[b * 33 + 24 + j] + gx[gxb + 3 * H_];
            const float cp = e ? creg1 : creg0;
            const float cn = sigf(gf) * cp + sigf(gi) * tanhfast(gg);
            if (e) creg1 = cn; else creg0 = cn;
            const float hv = sigf(go) * tanhfast(cn);
            h_out[off] = hv;
            const __nv_bfloat16 hhi = __float2bfloat16(hv);
            g_hh[outb][off] = hhi;
            g_hl[outb][off] = __float2bfloat16(hv - __bfloat162float(hhi));
            if (t == 0) {
                out[(size_t)T_ * B_ * H_ + off]            = hv;   // hT
                out[(size_t)T_ * B_ * H_ + B_ * H_ + off]  = cn;   // cT
            }
        }

        if (t > 0) grid_barrier();
    }
}

extern "C" void kernel_launch(void* const* d_in, const int* in_sizes, int n_in,
                              void* d_out, int out_size)
{
    const float* x   = (const float*)d_in[0];
    const float* h0  = (const float*)d_in[1];
    const float* c0  = (const float*)d_in[2];
    const float* Wih = (const float*)d_in[3];
    const float* Whh = (const float*)d_in[4];
    const float* bih = (const float*)d_in[5];
    const float* bhh = (const float*)d_in[6];
    float* out = (float*)d_out;

    cudaFuncSetAttribute(lstm_persist,
                         cudaFuncAttributeMaxDynamicSharedMemorySize, SMEM_TOT);

    split_whh_kernel<<<4096, 1024>>>(Whh);
    split_h0_kernel<<<64, 1024>>>(h0);

    dim3 gA(NG_ / 128, M_ / 128);
    gemm_x_kernel<<<gA, 256>>>(x, Wih, bih, bhh);

    lstm_persist<<<NBLK, 256, SMEM_TOT>>>(c0, out);
}

// round 17
// speedup vs baseline: 2.7927x; 1.3451x over previous
#include <cuda_runtime.h>
#include <cuda_bf16.h>
#include <stdint.h>
#include <math.h>

#define T_  512
#define B_  64
#define I_  1024
#define H_  1024
#define NG_ 4096               // 4*H
#define M_  (T_ * B_)          // 32768
#define NBLK 128

// ---------------- scratch (__device__ globals; no allocations allowed) -------
__device__ float g_gx[(size_t)M_ * NG_];              // x@W_ih^T + biases (fp32)
__device__ __nv_bfloat16 g_wh_hi[(size_t)NG_ * H_];   // Whh bf16 hi
__device__ __nv_bfloat16 g_wh_lo[(size_t)NG_ * H_];   // Whh bf16 lo
__device__ __nv_bfloat16 g_wi_hi[(size_t)NG_ * I_];   // Wih bf16 hi
__device__ __nv_bfloat16 g_wi_lo[(size_t)NG_ * I_];   // Wih bf16 lo
__device__ __nv_bfloat16 g_xh[(size_t)M_ * I_];       // x bf16 hi
__device__ __nv_bfloat16 g_xl[(size_t)M_ * I_];       // x bf16 lo
__device__ __nv_bfloat16 g_hh[2][B_ * H_];            // h bf16 hi (ping-pong)
__device__ __nv_bfloat16 g_hl[2][B_ * H_];            // h bf16 lo (ping-pong)
__device__ unsigned g_bar_count;                      // grid barrier state
__device__ volatile unsigned g_bar_gen;

// ---------------- helpers ----------------------------------------------------
static __device__ __forceinline__ float sigf(float x) {
    return __fdividef(1.f, 1.f + __expf(-x));
}
static __device__ __forceinline__ float tanhfast(float x) {
    return 2.f * __fdividef(1.f, 1.f + __expf(-2.f * x)) - 1.f;
}
static __device__ __forceinline__ uint32_t smem_u32(const void* p) {
    uint32_t a;
    asm("{ .reg .u64 t; cvta.to.shared.u64 t, %1; cvt.u32.u64 %0, t; }" : "=r"(a) : "l"(p));
    return a;
}

// ---------------- portable tensor-core + cp.async (sm_80 PTX) ----------------
#define LDSM4(r, addr) \
    asm volatile("ldmatrix.sync.aligned.m8n8.x4.shared.b16 {%0,%1,%2,%3}, [%4];" \
        : "=r"((r)[0]), "=r"((r)[1]), "=r"((r)[2]), "=r"((r)[3]) : "r"(addr))

#define MMA16816(d, a, b0r, b1r) \
    asm volatile("mma.sync.aligned.m16n8k16.row.col.f32.bf16.bf16.f32 " \
        "{%0,%1,%2,%3}, {%4,%5,%6,%7}, {%8,%9}, {%0,%1,%2,%3};" \
        : "+f"((d)[0]), "+f"((d)[1]), "+f"((d)[2]), "+f"((d)[3]) \
        : "r"((a)[0]), "r"((a)[1]), "r"((a)[2]), "r"((a)[3]), "r"(b0r), "r"(b1r))

#define CPA16(dst, src) \
    asm volatile("cp.async.cg.shared.global [%0], [%1], 16;" :: "r"(dst), "l"(src))
#define CPA_COMMIT() asm volatile("cp.async.commit_group;" ::: "memory")
#define CPA_WAIT(n)  asm volatile("cp.async.wait_group %0;" :: "n"(n) : "memory")

// ---------------- bf16 hi/lo split kernels -----------------------------------
__global__ void split_whh_kernel(const float* __restrict__ W)
{
    const size_t i = (size_t)blockIdx.x * 1024 + threadIdx.x;   // 4096 x 1024
    const float w = W[i];
    const __nv_bfloat16 hi = __float2bfloat16(w);
    g_wh_hi[i] = hi;
    g_wh_lo[i] = __float2bfloat16(w - __bfloat162float(hi));
}
__global__ void split_wih_kernel(const float* __restrict__ W)
{
    const size_t i = (size_t)blockIdx.x * 1024 + threadIdx.x;   // 4096 x 1024
    const float w = W[i];
    const __nv_bfloat16 hi = __float2bfloat16(w);
    g_wi_hi[i] = hi;
    g_wi_lo[i] = __float2bfloat16(w - __bfloat162float(hi));
}
__global__ void split_x_kernel(const float* __restrict__ X)
{
    const size_t i = (size_t)blockIdx.x * 1024 + threadIdx.x;   // 32768 x 1024
    const float v = X[i];
    const __nv_bfloat16 hi = __float2bfloat16(v);
    g_xh[i] = hi;
    g_xl[i] = __float2bfloat16(v - __bfloat162float(hi));
}
__global__ void split_h0_kernel(const float* __restrict__ h0)
{
    const int i = blockIdx.x * 1024 + threadIdx.x;              // 64 x 1024
    const float v = h0[i];
    const __nv_bfloat16 hi = __float2bfloat16(v);
    g_hh[0][i] = hi;
    g_hl[0][i] = __float2bfloat16(v - __bfloat162float(hi));
}

// =====================================================================
// Kernel A (tensor cores): Gx = X @ Wih^T + (bih+bhh)
// M=32768, N=4096, K=1024. Block tile 128x128, K-chunk 64, 2-stage
// cp.async. 8 warps: warp (m 2) x (n 4), warp tile 64x32.
// bf16 hi/lo 3-term (Xh*Wh + Xh*Wl + Xl*Wh).
// =====================================================================
#define GX_STAGE 73728     // 4 buffers x 128 rows x 144B
#define GX_AH 0
#define GX_AL 18432
#define GX_BH 36864
#define GX_BL 55296

__global__ __launch_bounds__(256)
void gemm_x_mma(const float* __restrict__ bih, const float* __restrict__ bhh)
{
    extern __shared__ __align__(1024) char sm[];
    const uint32_t smb = smem_u32(sm);
    const int tid  = threadIdx.x;
    const int warp = tid >> 5;
    const int lane = tid & 31;
    const int n0 = blockIdx.x * 128;
    const int m0 = blockIdx.y * 128;
    const int wm = (warp & 1) * 64;
    const int wn = (warp >> 1) * 32;

    // loader: each thread 4 consecutive 16B segs per buffer
    const int lr = tid >> 1;          // row 0..127
    const int ls = (tid & 1) * 4;     // seg 0 or 4 (of 8)

    const __nv_bfloat16* srcAh = g_xh + (size_t)(m0 + lr) * I_ + ls * 8;
    const __nv_bfloat16* srcAl = g_xl + (size_t)(m0 + lr) * I_ + ls * 8;
    const __nv_bfloat16* srcBh = g_wi_hi + (size_t)(n0 + lr) * I_ + ls * 8;
    const __nv_bfloat16* srcBl = g_wi_lo + (size_t)(n0 + lr) * I_ + ls * 8;
    const uint32_t ldst = lr * 144 + ls * 16;

    // ldmatrix offsets
    uint32_t aOff[4], bOff[2];
    #pragma unroll
    for (int mt = 0; mt < 4; ++mt)
        aOff[mt] = (wm + mt * 16 + (lane & 15)) * 144 + (lane >> 4) * 16;
    #pragma unroll
    for (int nb = 0; nb < 2; ++nb)
        bOff[nb] = (wn + nb * 16 + ((lane >> 3) & 1) * 8 + (lane & 7)) * 144 +
                   (lane >> 4) * 16;

    float acc[4][4][4];
    #pragma unroll
    for (int mt = 0; mt < 4; ++mt)
        #pragma unroll
        for (int j = 0; j < 4; ++j)
            #pragma unroll
            for (int q = 0; q < 4; ++q) acc[mt][j][q] = 0.f;

    // prologue: stage 0 = chunk 0
    {
        const uint32_t d = smb + ldst;
        #pragma unroll
        for (int i = 0; i < 4; ++i) {
            CPA16(d + GX_AH + i * 16, srcAh + i * 8);
            CPA16(d + GX_AL + i * 16, srcAl + i * 8);
            CPA16(d + GX_BH + i * 16, srcBh + i * 8);
            CPA16(d + GX_BL + i * 16, srcBl + i * 8);
        }
        CPA_COMMIT();
    }

    for (int c = 0; c < 16; ++c) {
        if (c + 1 < 16) {
            const uint32_t d = smb + ((c + 1) & 1) * GX_STAGE + ldst;
            const size_t ko = (size_t)(c + 1) * 64;
            #pragma unroll
            for (int i = 0; i < 4; ++i) {
                CPA16(d + GX_AH + i * 16, srcAh + ko + i * 8);
                CPA16(d + GX_AL + i * 16, srcAl + ko + i * 8);
                CPA16(d + GX_BH + i * 16, srcBh + ko + i * 8);
                CPA16(d + GX_BL + i * 16, srcBl + ko + i * 8);
            }
            CPA_COMMIT();
            CPA_WAIT(1);
        } else {
            CPA_WAIT(0);
        }
        __syncthreads();

        const uint32_t stb = smb + (c & 1) * GX_STAGE;
        #pragma unroll
        for (int kk = 0; kk < 4; ++kk) {
            uint32_t ah[4][4], al[4][4];
            #pragma unroll
            for (int mt = 0; mt < 4; ++mt) {
                LDSM4(ah[mt], stb + GX_AH + aOff[mt] + kk * 32);
                LDSM4(al[mt], stb + GX_AL + aOff[mt] + kk * 32);
            }
            #pragma unroll
            for (int nb = 0; nb < 2; ++nb) {
                uint32_t bh[4], bl[4];
                LDSM4(bh, stb + GX_BH + bOff[nb] + kk * 32);
                LDSM4(bl, stb + GX_BL + bOff[nb] + kk * 32);
                #pragma unroll
                for (int mt = 0; mt < 4; ++mt) {
                    MMA16816(acc[mt][nb * 2],     ah[mt], bh[0], bh[2]);
                    MMA16816(acc[mt][nb * 2 + 1], ah[mt], bh[1], bh[3]);
                    MMA16816(acc[mt][nb * 2],     ah[mt], bl[0], bl[2]);
                    MMA16816(acc[mt][nb * 2 + 1], ah[mt], bl[1], bl[3]);
                    MMA16816(acc[mt][nb * 2],     al[mt], bh[0], bh[2]);
                    MMA16816(acc[mt][nb * 2 + 1], al[mt], bh[1], bh[3]);
                }
            }
        }
        __syncthreads();
    }

    // epilogue: bias + store
    const int r0 = lane >> 2;
    const int cc0 = 2 * (lane & 3);
    float bv[4][2];
    #pragma unroll
    for (int j = 0; j < 4; ++j) {
        const int col = n0 + wn + (j >> 1) * 16 + (j & 1) * 8 + cc0;
        bv[j][0] = bih[col] + bhh[col];
        bv[j][1] = bih[col + 1] + bhh[col + 1];
    }
    #pragma unroll
    for (int mt = 0; mt < 4; ++mt) {
        const int mrow = m0 + wm + mt * 16 + r0;
        #pragma unroll
        for (int j = 0; j < 4; ++j) {
            const int col = n0 + wn + (j >> 1) * 16 + (j & 1) * 8 + cc0;
            *(float2*)&g_gx[(size_t)mrow * NG_ + col] =
                make_float2(acc[mt][j][0] + bv[j][0], acc[mt][j][1] + bv[j][1]);
            *(float2*)&g_gx[(size_t)(mrow + 8) * NG_ + col] =
                make_float2(acc[mt][j][2] + bv[j][0], acc[mt][j][3] + bv[j][1]);
        }
    }
}

// =====================================================================
// Persistent reverse-scan kernel (structure unchanged from R14; adds
// early gx prefetch to hide epilogue L2 latency).
// =====================================================================
#define OFF_BH 0
#define OFF_BL 66048
#define OFF_A  132096          // 4 stages x 18432 (hi 9216 + lo 9216)
#define OFF_C  205824          // 64 x 33 floats
#define SMEM_TOT 214272
#define BROW_STRIDE 2064       // 1024 bf16 + 8 pad
#define AROW_STRIDE 144        // 64 bf16 + 8 pad
#define STAGE_BYTES 18432

static __device__ __forceinline__ void grid_barrier()
{
    __threadfence();
    __syncthreads();
    if (threadIdx.x == 0) {
        const unsigned seen = g_bar_gen;
        if (atomicAdd(&g_bar_count, 1) == NBLK - 1) {
            atomicExch(&g_bar_count, 0);
            __threadfence();
            g_bar_gen = seen + 1;
        } else {
            while (g_bar_gen == seen) { }
            __threadfence();
        }
    }
    __syncthreads();
}

__global__ __launch_bounds__(256)
void lstm_persist(const float* __restrict__ cinit, float* __restrict__ out)
{
    extern __shared__ __align__(1024) char sm[];
    const uint32_t smb = smem_u32(sm);
    const int tid  = threadIdx.x;
    const int warp = tid >> 5;
    const int lane = tid & 31;
    const int n0   = blockIdx.x * 8;

    // ---- load resident Whh slice (hi/lo) ----
    for (int i = tid; i < 4096; i += 256) {
        const int r = i >> 7, s = i & 127;
        const size_t grow = (size_t)((r >> 3) * H_ + n0 + (r & 7)) * H_;
        *(uint4*)(sm + OFF_BH + r * BROW_STRIDE + s * 16) =
            *(const uint4*)(g_wh_hi + grow + s * 8);
        *(uint4*)(sm + OFF_BL + r * BROW_STRIDE + s * 16) =
            *(const uint4*)(g_wh_lo + grow + s * 8);
    }

    const int wm = (warp & 3) * 16;
    const int wn = (warp >> 2) * 16;
    const int brow = wn + ((lane >> 3) & 1) * 8 + (lane & 7);
    const uint32_t bBaseH = smb + OFF_BH + brow * BROW_STRIDE + (lane >> 4) * 16;
    const uint32_t bBaseL = smb + OFF_BL + brow * BROW_STRIDE + (lane >> 4) * 16;
    const uint32_t aFrag  = (wm + (lane & 15)) * AROW_STRIDE + (lane >> 4) * 16;

    const int arow = tid >> 2;
    const int segB = (tid & 3) * 16;
    const int segE = (tid & 3) * 8;

    const int b0 = (tid * 2) >> 3,     j0 = (tid * 2) & 7;
    const int b1 = (tid * 2 + 1) >> 3, j1 = (tid * 2 + 1) & 7;
    const int off0 = b0 * H_ + n0 + j0;
    const int off1 = b1 * H_ + n0 + j1;
    const size_t gxo0 = (size_t)b0 * NG_ + n0 + j0;
    const size_t gxo1 = (size_t)b1 * NG_ + n0 + j1;
    float creg0 = cinit[off0];
    float creg1 = cinit[off1];

    float* sC = (float*)(sm + OFF_C);
    __syncthreads();

    for (int t = T_ - 1; t >= 0; --t) {
        const int inb = (t + 1) & 1, outb = t & 1;
        const __nv_bfloat16* Ah = g_hh[inb] + (size_t)arow * H_ + segE;
        const __nv_bfloat16* Al = g_hl[inb] + (size_t)arow * H_ + segE;
        const uint32_t aDst = smb + OFF_A + arow * AROW_STRIDE + segB;

        // ---- early gx prefetch (independent of h) ----
        const float* gx = g_gx + (size_t)t * B_ * NG_;
        float pf[8];
        pf[0] = __ldg(gx + gxo0);
        pf[1] = __ldg(gx + gxo0 + H_);
        pf[2] = __ldg(gx + gxo0 + 2 * H_);
        pf[3] = __ldg(gx + gxo0 + 3 * H_);
        pf[4] = __ldg(gx + gxo1);
        pf[5] = __ldg(gx + gxo1 + H_);
        pf[6] = __ldg(gx + gxo1 + 2 * H_);
        pf[7] = __ldg(gx + gxo1 + 3 * H_);

        // prologue: chunks 0..2 into stages 0..2
        #pragma unroll
        for (int s = 0; s < 3; ++s) {
            const uint32_t d = aDst + s * STAGE_BYTES;
            CPA16(d,             Ah + s * 64);
            CPA16(d + 64,        Ah + s * 64 + 32);
            CPA16(d + 9216,      Al + s * 64);
            CPA16(d + 9216 + 64, Al + s * 64 + 32);
            CPA_COMMIT();
        }

        float acc0[4] = {0.f, 0.f, 0.f, 0.f};
        float acc1[4] = {0.f, 0.f, 0.f, 0.f};

        for (int c = 0; c < 16; ++c) {
            if (c < 14)       CPA_WAIT(2);
            else if (c == 14) CPA_WAIT(1);
            else              CPA_WAIT(0);
            __syncthreads();
            if (c + 3 < 16) {
                const int cc = c + 3;
                const uint32_t d = aDst + (cc & 3) * STAGE_BYTES;
                CPA16(d,             Ah + cc * 64);
                CPA16(d + 64,        Ah + cc * 64 + 32);
                CPA16(d + 9216,      Al + cc * 64);
                CPA16(d + 9216 + 64, Al + cc * 64 + 32);
                CPA_COMMIT();
            }
            const uint32_t aH = smb + OFF_A + (c & 3) * STAGE_BYTES + aFrag;
            const uint32_t aL = aH + 9216;
            const uint32_t bH = bBaseH + c * 128;
            const uint32_t bL = bBaseL + c * 128;
            #pragma unroll
            for (int ks = 0; ks < 4; ++ks) {
                uint32_t ah[4], al[4], bh[4], bl[4];
                LDSM4(ah, aH + ks * 32);
                LDSM4(al, aL + ks * 32);
                LDSM4(bh, bH + ks * 32);
                LDSM4(bl, bL + ks * 32);
                MMA16816(acc0, ah, bh[0], bh[2]);
                MMA16816(acc1, ah, bh[1], bh[3]);
                MMA16816(acc0, ah, bl[0], bl[2]);
                MMA16816(acc1, ah, bl[1], bl[3]);
                MMA16816(acc0, al, bh[0], bh[2]);
                MMA16816(acc1, al, bh[1], bh[3]);
            }
        }

        // ---- stage C tile ----
        {
            const int r0 = wm + (lane >> 2);
            const int cc = wn + 2 * (lane & 3);
            sC[r0 * 33 + cc]           = acc0[0];
            sC[r0 * 33 + cc + 1]       = acc0[1];
            sC[(r0 + 8) * 33 + cc]     = acc0[2];
            sC[(r0 + 8) * 33 + cc + 1] = acc0[3];
            sC[r0 * 33 + cc + 8]       = acc1[0];
            sC[r0 * 33 + cc + 9]       = acc1[1];
            sC[(r0 + 8) * 33 + cc + 8] = acc1[2];
            sC[(r0 + 8) * 33 + cc + 9] = acc1[3];
        }
        __syncthreads();

        // ---- cell update (2 elems/thread, c-state in registers) ----
        float* h_out = out + (size_t)t * B_ * H_;
        #pragma unroll
        for (int e = 0; e < 2; ++e) {
            const int b = e ? b1 : b0;
            const int j = e ? j1 : j0;
            const int off = e ? off1 : off0;
            const float gi = sC[b * 33 + j]      + pf[e * 4 + 0];
            const float gf = sC[b * 33 + 8 + j]  + pf[e * 4 + 1];
            const float gg = sC[b * 33 + 16 + j] + pf[e * 4 + 2];
            const float go = sC[b * 33 + 24 + j] + pf[e * 4 + 3];
            const float cp = e ? creg1 : creg0;
            const float cn = sigf(gf) * cp + sigf(gi) * tanhfast(gg);
            if (e) creg1 = cn; else creg0 = cn;
            const float hv = sigf(go) * tanhfast(cn);
            h_out[off] = hv;
            const __nv_bfloat16 hhi = __float2bfloat16(hv);
            g_hh[outb][off] = hhi;
            g_hl[outb][off] = __float2bfloat16(hv - __bfloat162float(hhi));
            if (t == 0) {
                out[(size_t)T_ * B_ * H_ + off]           = hv;   // hT
                out[(size_t)T_ * B_ * H_ + B_ * H_ + off] = cn;   // cT
            }
        }

        if (t > 0) grid_barrier();
    }
}

extern "C" void kernel_launch(void* const* d_in, const int* in_sizes, int n_in,
                              void* d_out, int out_size)
{
    const float* x   = (const float*)d_in[0];
    const float* h0  = (const float*)d_in[1];
    const float* c0  = (const float*)d_in[2];
    const float* Wih = (const float*)d_in[3];
    const float* Whh = (const float*)d_in[4];
    const float* bih = (const float*)d_in[5];
    const float* bhh = (const float*)d_in[6];
    float* out = (float*)d_out;

    cudaFuncSetAttribute(lstm_persist,
                         cudaFuncAttributeMaxDynamicSharedMemorySize, SMEM_TOT);
    cudaFuncSetAttribute(gemm_x_mma,
                         cudaFuncAttributeMaxDynamicSharedMemorySize, 2 * GX_STAGE);

    split_x_kernel<<<M_, 1024>>>(x);
    split_wih_kernel<<<NG_, 1024>>>(Wih);
    split_whh_kernel<<<NG_, 1024>>>(Whh);
    split_h0_kernel<<<B_, 1024>>>(h0);

    dim3 gA(NG_ / 128, M_ / 128);       // 32 x 256
    gemm_x_mma<<<gA, 256, 2 * GX_STAGE>>>(bih, bhh);

    lstm_persist<<<NBLK, 256, SMEM_TOT>>>(c0, out);
}